// round 14
// baseline (speedup 1.0000x reference)
#include <cuda_runtime.h>
#include <cuda_fp16.h>

#define NN 100000
#define NE 1600000
#define FD 128
#define NB 391            // ceil(NN / 256)
#define SA_STRIDE 136     // 128 + 8 halves pad -> conflict-free ldmatrix
#define SW_STRIDE 136
#define ROWS_PER_BLK 128  // 2 chunks of 64 rows

// ---- scratch (static device arrays; no runtime alloc allowed) ----
static __device__ __half g_xh[(size_t)NN * FD];   // fp16(x * nsrc)
static __device__ __half g_sh[(size_t)NN * FD];   // fp16(ndst * agg(xh))  (GEMM input)
static __device__ __half g_Wh1[FD * FD];          // W1 in fp16
static __device__ int    g_degout[NN];
static __device__ int    g_degin[NN];
static __device__ float  g_nsrc[NN];
static __device__ float  g_ndst[NN];
static __device__ int    g_rowptr[NN];            // bucket base (arbitrary order)
static __device__ int    g_cursor[NN];
static __device__ int    g_csr[NE];               // src ids bucketed by dst
static __device__ int    g_total;                 // global bucket cursor
static __device__ float  g_u1[FD];                // W2 @ Wp[:128]
static __device__ float  g_u2[FD];                // W2 @ Wp[128:]
static __device__ float  g_cA, g_cB;              // dot(b2,Wp1), dot(b2,Wp2)
static __device__ float2 g_pq[NN];                // per-node {p,q} projections
static __device__ float  g_a[NN];
static __device__ float  g_c[NN];

// ---- degree counting ----
__global__ void count_k(const int* __restrict__ src, const int* __restrict__ dst) {
    int e = blockIdx.x * blockDim.x + threadIdx.x;
    if (e < NE) {
        atomicAdd(&g_degout[src[e]], 1);
        atomicAdd(&g_degin[dst[e]], 1);
    }
}

__global__ void norm_k() {
    int i = blockIdx.x * blockDim.x + threadIdx.x;
    if (i == 0) g_total = 0;
    if (i < NN) {
        g_nsrc[i] = rsqrtf(fmaxf((float)g_degout[i], 1.0f));
        g_ndst[i] = rsqrtf(fmaxf((float)g_degin[i], 1.0f));
    }
}

// ---- xh = fp16(x * nsrc) ----
__global__ void convx_k(const float* __restrict__ x) {
    int idx = blockIdx.x * 256 + threadIdx.x;
    if (idx >= NN * 16) return;
    int r = idx >> 4;
    int c8 = (idx & 15) << 3;
    float ns = g_nsrc[r];
    float4 f0 = *reinterpret_cast<const float4*>(x + (size_t)r * FD + c8);
    float4 f1 = *reinterpret_cast<const float4*>(x + (size_t)r * FD + c8 + 4);
    __half2 h0 = __floats2half2_rn(f0.x * ns, f0.y * ns);
    __half2 h1 = __floats2half2_rn(f0.z * ns, f0.w * ns);
    __half2 h2 = __floats2half2_rn(f1.x * ns, f1.y * ns);
    __half2 h3 = __floats2half2_rn(f1.z * ns, f1.w * ns);
    uint4 st;
    st.x = *reinterpret_cast<unsigned*>(&h0);
    st.y = *reinterpret_cast<unsigned*>(&h1);
    st.z = *reinterpret_cast<unsigned*>(&h2);
    st.w = *reinterpret_cast<unsigned*>(&h3);
    *reinterpret_cast<uint4*>(g_xh + (size_t)r * FD + c8) = st;
}

// ---- W fp32 -> fp16 ----
__global__ void packW_k(const float* __restrict__ W, __half* __restrict__ Wh) {
    int i = blockIdx.x * blockDim.x + threadIdx.x;
    if (i < FD * FD) Wh[i] = __float2half(__ldg(W + i));
}

// ---- layer-2 collapse precompute: u1 = W2@Wp1, u2 = W2@Wp2, cA, cB ----
__global__ void prep_k(const float* __restrict__ W2, const float* __restrict__ Wp,
                       const float* __restrict__ b2) {
    int t = threadIdx.x;   // 128 threads
    float s1 = 0.f, s2 = 0.f;
#pragma unroll 4
    for (int o = 0; o < FD; o++) {
        float w = __ldg(W2 + t * FD + o);
        s1 += w * __ldg(Wp + o);
        s2 += w * __ldg(Wp + FD + o);
    }
    g_u1[t] = s1;
    g_u2[t] = s2;

    float bv = __ldg(b2 + t);
    float c1 = bv * __ldg(Wp + t);
    float c2 = bv * __ldg(Wp + FD + t);
    __shared__ float sh1[128], sh2[128];
    sh1[t] = c1; sh2[t] = c2;
    __syncthreads();
    for (int off = 64; off > 0; off >>= 1) {
        if (t < off) { sh1[t] += sh1[t + off]; sh2[t] += sh2[t + off]; }
        __syncthreads();
    }
    if (t == 0) { g_cA = sh1[0]; g_cB = sh2[0]; }
}

// ---- fused CSR base assignment: block scan + one global atomic per block ----
__global__ void rowbase_k() {
    int i = blockIdx.x * 256 + threadIdx.x;
    int lane = threadIdx.x & 31, wid = threadIdx.x >> 5;
    int v = (i < NN) ? g_degin[i] : 0;
    int incl = v;
#pragma unroll
    for (int off = 1; off < 32; off <<= 1) {
        int n = __shfl_up_sync(0xffffffffu, incl, off);
        if (lane >= off) incl += n;
    }
    __shared__ int ws[8];
    __shared__ int sbase;
    if (lane == 31) ws[wid] = incl;
    __syncthreads();
    if (threadIdx.x == 0) {
        int run = 0;
#pragma unroll
        for (int w = 0; w < 8; w++) { int t = ws[w]; ws[w] = run; run += t; }
        sbase = atomicAdd(&g_total, run);
    }
    __syncthreads();
    int beg = sbase + incl - v + ws[wid];
    if (i < NN) {
        g_rowptr[i] = beg;
        g_cursor[i] = beg;
    }
}

__global__ void fill_k(const int* __restrict__ src, const int* __restrict__ dst) {
    int e = blockIdx.x * blockDim.x + threadIdx.x;
    if (e < NE) {
        int d = dst[e];
        int pos = atomicAdd(&g_cursor[d], 1);
        g_csr[pos] = src[e];
    }
}

// ---- HMMA helpers ----
__device__ __forceinline__ unsigned smem_u32(const void* p) {
    return (unsigned)__cvta_generic_to_shared(p);
}

__device__ __forceinline__ void ldsm_x4(unsigned& r0, unsigned& r1, unsigned& r2,
                                        unsigned& r3, unsigned addr) {
    asm volatile("ldmatrix.sync.aligned.m8n8.x4.shared.b16 {%0,%1,%2,%3}, [%4];"
                 : "=r"(r0), "=r"(r1), "=r"(r2), "=r"(r3) : "r"(addr));
}

__device__ __forceinline__ void ldsm_x4_t(unsigned& r0, unsigned& r1, unsigned& r2,
                                          unsigned& r3, unsigned addr) {
    asm volatile("ldmatrix.sync.aligned.m8n8.x4.trans.shared.b16 {%0,%1,%2,%3}, [%4];"
                 : "=r"(r0), "=r"(r1), "=r"(r2), "=r"(r3) : "r"(addr));
}

__device__ __forceinline__ void mma16816(float4& c, unsigned a0, unsigned a1,
                                         unsigned a2, unsigned a3,
                                         unsigned b0, unsigned b1) {
    asm volatile("mma.sync.aligned.m16n8k16.row.col.f32.f16.f16.f32 "
                 "{%0,%1,%2,%3}, {%4,%5,%6,%7}, {%8,%9}, {%0,%1,%2,%3};"
                 : "+f"(c.x), "+f"(c.y), "+f"(c.z), "+f"(c.w)
                 : "r"(a0), "r"(a1), "r"(a2), "r"(a3), "r"(b0), "r"(b1));
}

__device__ __forceinline__ uint4 load_fragh(const __half* __restrict__ in, int gr, int c8) {
    if (gr < NN) return *reinterpret_cast<const uint4*>(in + (size_t)gr * FD + c8);
    return make_uint4(0u, 0u, 0u, 0u);
}

// ---- warp-per-node CSR accumulate over fp16 xh rows (fp32 accum) ----
__device__ __forceinline__ float4 csr_accum(int node, int lane) {
    int beg = g_rowptr[node];
    int end = beg + g_degin[node];
    float4 acc = make_float4(0.f, 0.f, 0.f, 0.f);
    int j = beg;
    for (; j + 4 <= end; j += 4) {
        int s0 = __ldg(g_csr + j);
        int s1 = __ldg(g_csr + j + 1);
        int s2 = __ldg(g_csr + j + 2);
        int s3 = __ldg(g_csr + j + 3);
        uint2 u0 = *reinterpret_cast<const uint2*>(g_xh + (size_t)s0 * FD + lane * 4);
        uint2 u1 = *reinterpret_cast<const uint2*>(g_xh + (size_t)s1 * FD + lane * 4);
        uint2 u2 = *reinterpret_cast<const uint2*>(g_xh + (size_t)s2 * FD + lane * 4);
        uint2 u3 = *reinterpret_cast<const uint2*>(g_xh + (size_t)s3 * FD + lane * 4);
        float2 a0 = __half22float2(*reinterpret_cast<__half2*>(&u0.x));
        float2 b0 = __half22float2(*reinterpret_cast<__half2*>(&u0.y));
        float2 a1 = __half22float2(*reinterpret_cast<__half2*>(&u1.x));
        float2 b1 = __half22float2(*reinterpret_cast<__half2*>(&u1.y));
        float2 a2 = __half22float2(*reinterpret_cast<__half2*>(&u2.x));
        float2 b2 = __half22float2(*reinterpret_cast<__half2*>(&u2.y));
        float2 a3 = __half22float2(*reinterpret_cast<__half2*>(&u3.x));
        float2 b3 = __half22float2(*reinterpret_cast<__half2*>(&u3.y));
        acc.x += (a0.x + a1.x) + (a2.x + a3.x);
        acc.y += (a0.y + a1.y) + (a2.y + a3.y);
        acc.z += (b0.x + b1.x) + (b2.x + b3.x);
        acc.w += (b0.y + b1.y) + (b2.y + b3.y);
    }
    for (; j < end; j++) {
        int s = __ldg(g_csr + j);
        uint2 u = *reinterpret_cast<const uint2*>(g_xh + (size_t)s * FD + lane * 4);
        float2 a = __half22float2(*reinterpret_cast<__half2*>(&u.x));
        float2 b = __half22float2(*reinterpret_cast<__half2*>(&u.y));
        acc.x += a.x; acc.y += a.y; acc.z += b.x; acc.w += b.y;
    }
    return acc;
}

// ---- layer-1 aggregate over xh: s[w] = fp16(ndst[w] * Sum xh_j) ----
__global__ __launch_bounds__(256) void gather1x_k() {
    int w = (blockIdx.x * 256 + threadIdx.x) >> 5;
    if (w >= NN) return;
    int lane = threadIdx.x & 31;
    float4 acc = csr_accum(w, lane);
    float nd = g_ndst[w];
    __half2 h01 = __floats2half2_rn(acc.x * nd, acc.y * nd);
    __half2 h23 = __floats2half2_rn(acc.z * nd, acc.w * nd);
    uint2 st;
    st.x = *reinterpret_cast<unsigned*>(&h01);
    st.y = *reinterpret_cast<unsigned*>(&h23);
    *reinterpret_cast<uint2*>(g_sh + (size_t)w * FD + lane * 4) = st;
}

// ---- GEMM + fused projection: z = relu(s@W1 + b1) (in accumulators only),
// p = nsrc*dot(z,u1), q = nsrc*dot(z,u2) -> g_pq. z is never stored. ----
__global__ __launch_bounds__(256) void gemmz_k(const __half* __restrict__ Wh,
                                               const float* __restrict__ b1) {
    __shared__ __half sA[64 * SA_STRIDE];
    __shared__ __half sW[FD * SW_STRIDE];
    __shared__ float sP[64], sQ[64];
    const int tid = threadIdx.x;
    const int blk0 = blockIdx.x * ROWS_PER_BLK;

    for (int i = tid; i < FD * 16; i += 256) {
        int r = i >> 4;
        int c8 = (i & 15) << 3;
        uint4 v = *reinterpret_cast<const uint4*>(Wh + r * FD + c8);
        *reinterpret_cast<uint4*>(&sW[r * SW_STRIDE + c8]) = v;
    }

    int rs[4];
    const int cs = (tid & 15) << 3;
#pragma unroll
    for (int p = 0; p < 4; p++) rs[p] = (tid + p * 256) >> 4;

    const int lane = tid & 31;
    const int wid = tid >> 5;
    const int mA = (wid & 1) << 4;
    const int n0 = (wid >> 1) << 5;
    const int lm = lane >> 3;
    const int lr = lane & 7;
    const int arowA = mA + ((lm & 1) << 3) + lr;
    const int koff = (lm >> 1) << 3;

    uint4 cur[4];
#pragma unroll
    for (int p = 0; p < 4; p++) cur[p] = load_fragh(g_sh, blk0 + rs[p], cs);

#pragma unroll
    for (int chunk = 0; chunk < 2; chunk++) {
        const int row0 = blk0 + chunk * 64;
        __syncthreads();
#pragma unroll
        for (int p = 0; p < 4; p++)
            *reinterpret_cast<uint4*>(&sA[rs[p] * SA_STRIDE + cs]) = cur[p];
        if (chunk == 0) {
#pragma unroll
            for (int p = 0; p < 4; p++) cur[p] = load_fragh(g_sh, row0 + 64 + rs[p], cs);
        }
        if (tid < 64) { sP[tid] = 0.f; sQ[tid] = 0.f; }
        __syncthreads();

        float4 cA[4], cB[4];
#pragma unroll
        for (int j = 0; j < 4; j++) {
            cA[j] = make_float4(0.f, 0.f, 0.f, 0.f);
            cB[j] = make_float4(0.f, 0.f, 0.f, 0.f);
        }

#pragma unroll
        for (int ks = 0; ks < 8; ks++) {
            int k0 = ks << 4;
            unsigned aA0, aA1, aA2, aA3, aB0, aB1, aB2, aB3;
            ldsm_x4(aA0, aA1, aA2, aA3, smem_u32(&sA[arowA * SA_STRIDE + k0 + koff]));
            ldsm_x4(aB0, aB1, aB2, aB3, smem_u32(&sA[(arowA + 32) * SA_STRIDE + k0 + koff]));
#pragma unroll
            for (int j = 0; j < 2; j++) {
                int n = n0 + (j << 4);
                unsigned b0r, b1r, b2r, b3r;
                ldsm_x4_t(b0r, b1r, b2r, b3r,
                          smem_u32(&sW[(k0 + ((lm & 1) << 3) + lr) * SW_STRIDE + n + koff]));
                mma16816(cA[2 * j],     aA0, aA1, aA2, aA3, b0r, b1r);
                mma16816(cA[2 * j + 1], aA0, aA1, aA2, aA3, b2r, b3r);
                mma16816(cB[2 * j],     aB0, aB1, aB2, aB3, b0r, b1r);
                mma16816(cB[2 * j + 1], aB0, aB1, aB2, aB3, b2r, b3r);
            }
        }

        // epilogue: z = relu(c + b1), partial dots with u1/u2, reduce
#pragma unroll
        for (int t = 0; t < 2; t++) {
            float4* cc = (t == 0) ? cA : cB;
            const int lr0 = mA + t * 32 + (lane >> 2);
            const int lr1 = lr0 + 8;
            float pv0 = 0.f, qv0 = 0.f, pv1 = 0.f, qv1 = 0.f;
#pragma unroll
            for (int j = 0; j < 4; j++) {
                int col = n0 + (j << 3) + ((lane & 3) << 1);
                float2 bb = *reinterpret_cast<const float2*>(b1 + col);
                float2 u1c = *reinterpret_cast<const float2*>(g_u1 + col);
                float2 u2c = *reinterpret_cast<const float2*>(g_u2 + col);
                float z0 = fmaxf(cc[j].x + bb.x, 0.f);
                float z1 = fmaxf(cc[j].y + bb.y, 0.f);
                float z2 = fmaxf(cc[j].z + bb.x, 0.f);
                float z3 = fmaxf(cc[j].w + bb.y, 0.f);
                pv0 += z0 * u1c.x + z1 * u1c.y;
                qv0 += z0 * u2c.x + z1 * u2c.y;
                pv1 += z2 * u1c.x + z3 * u1c.y;
                qv1 += z2 * u2c.x + z3 * u2c.y;
            }
            // reduce over the 4 lanes sharing each row (lane&3)
#pragma unroll
            for (int off = 1; off <= 2; off <<= 1) {
                pv0 += __shfl_xor_sync(0xffffffffu, pv0, off);
                qv0 += __shfl_xor_sync(0xffffffffu, qv0, off);
                pv1 += __shfl_xor_sync(0xffffffffu, pv1, off);
                qv1 += __shfl_xor_sync(0xffffffffu, qv1, off);
            }
            if ((lane & 3) == 0) {
                atomicAdd(&sP[lr0], pv0);
                atomicAdd(&sQ[lr0], qv0);
                atomicAdd(&sP[lr1], pv1);
                atomicAdd(&sQ[lr1], qv1);
            }
        }
        __syncthreads();

        if (tid < 64) {
            int r = row0 + tid;
            if (r < NN) {
                float ns = g_nsrc[r];
                g_pq[r] = make_float2(ns * sP[tid], ns * sQ[tid]);
            }
        }
    }
}

// ---- layer-2 scalar aggregate: a[i] = nd[i]*Sum p[j] + cA (thread/node) ----
__global__ __launch_bounds__(256) void gather2s_k() {
    int i = blockIdx.x * 256 + threadIdx.x;
    if (i >= NN) return;
    int beg = g_rowptr[i];
    int end = beg + g_degin[i];
    float sp = 0.f, sq = 0.f;
    int j = beg;
    for (; j + 4 <= end; j += 4) {
        int s0 = __ldg(g_csr + j);
        int s1 = __ldg(g_csr + j + 1);
        int s2 = __ldg(g_csr + j + 2);
        int s3 = __ldg(g_csr + j + 3);
        float2 v0 = g_pq[s0];
        float2 v1 = g_pq[s1];
        float2 v2 = g_pq[s2];
        float2 v3 = g_pq[s3];
        sp += (v0.x + v1.x) + (v2.x + v3.x);
        sq += (v0.y + v1.y) + (v2.y + v3.y);
    }
    for (; j < end; j++) {
        float2 v = g_pq[__ldg(g_csr + j)];
        sp += v.x; sq += v.y;
    }
    float nd = g_ndst[i];
    g_a[i] = fmaf(nd, sp, g_cA);
    g_c[i] = fmaf(nd, sq, g_cB);
}

// ---- final per-edge score: sigmoid(a[src] + c[dst] + bp) ----
__global__ void edgescore_k(const int* __restrict__ src, const int* __restrict__ dst,
                            const float* __restrict__ bp, float* __restrict__ out) {
    int e = blockIdx.x * blockDim.x + threadIdx.x;
    if (e < NE) {
        float z = g_a[__ldg(src + e)] + g_c[__ldg(dst + e)] + __ldg(bp);
        out[e] = 1.0f / (1.0f + expf(-z));
    }
}

extern "C" void kernel_launch(void* const* d_in, const int* in_sizes, int n_in,
                              void* d_out, int out_size) {
    (void)in_sizes; (void)n_in; (void)out_size;
    const float* x  = (const float*)d_in[0];
    const float* W1 = (const float*)d_in[1];
    const float* b1 = (const float*)d_in[2];
    const float* W2 = (const float*)d_in[3];
    const float* b2 = (const float*)d_in[4];
    const float* Wp = (const float*)d_in[5];
    const float* bp = (const float*)d_in[6];
    const int* src  = (const int*)d_in[7];
    const int* dst  = (const int*)d_in[8];
    float* out = (float*)d_out;

    void *p_w1, *p_di, *p_do;
    cudaGetSymbolAddress(&p_w1, g_Wh1);
    cudaGetSymbolAddress(&p_di, g_degin);
    cudaGetSymbolAddress(&p_do, g_degout);

    cudaMemsetAsync(p_di, 0, sizeof(int) * NN);
    cudaMemsetAsync(p_do, 0, sizeof(int) * NN);

    // degrees + norms
    count_k<<<(NE + 255) / 256, 256>>>(src, dst);
    norm_k<<<(NN + 255) / 256, 256>>>();

    // xh = fp16(x * nsrc); CSR build (single-pass base assignment)
    convx_k<<<(NN * 16 + 255) / 256, 256>>>(x);
    rowbase_k<<<NB, 256>>>();
    fill_k<<<(NE + 255) / 256, 256>>>(src, dst);

    // aggregate xh -> s  (the big gather)
    gather1x_k<<<(NN * 32 + 255) / 256, 256>>>();

    // weights: W1 fp16, layer-2 collapse vectors
    packW_k<<<(FD * FD + 255) / 256, 256>>>(W1, (__half*)p_w1);
    prep_k<<<1, 128>>>(W2, Wp, b2);

    // GEMM + fused relu/bias/projection -> p,q per node (z never stored)
    gemmz_k<<<(NN + ROWS_PER_BLK - 1) / ROWS_PER_BLK, 256>>>((const __half*)p_w1, b1);

    // layer-2 scalar aggregate -> a,c ; then per-edge score
    gather2s_k<<<(NN + 255) / 256, 256>>>();
    edgescore_k<<<(NE + 255) / 256, 256>>>(src, dst, bp, out);
}